// round 5
// baseline (speedup 1.0000x reference)
#include <cuda_runtime.h>
#include <cuda_fp16.h>
#include <math.h>
#include <stdint.h>

// Problem constants
#define T_TOKENS 8192
#define D_DIM    1024
#define H_DIM    4096
#define R_DIM    512
#define E_NUM    8
#define SLOTS    (T_TOKENS * 2)
#define MAX_TILES 136
#define KR_DIM   3072   // router split-K: [xh|xh|xl] x [wh|wl|wh]

// ---------------- scratch (device globals; no allocation allowed) ----------
__device__ __half g_xsplit[T_TOKENS * KR_DIM];       // [xh|xh|xl]      50MB
__device__ __half g_wr1split[R_DIM * KR_DIM];        // [wh|wl|wh]*32    3MB
__device__ __half g_W1h[E_NUM * H_DIM * D_DIM];      // W1 fp16         67MB
__device__ __half g_W2h[E_NUM * D_DIM * H_DIM];      // W2 fp16         67MB
__device__ float  g_hrouter[T_TOKENS * R_DIM];       // gelu(x@Wr1^T+br1)
__device__ __half g_He[SLOTS * H_DIM];               // expert hidden  134MB
__device__ float  g_Y[SLOTS * D_DIM];                // expert output   67MB
__device__ int    g_expIdx[SLOTS];
__device__ float  g_expW[SLOTS];
__device__ int    g_counts[E_NUM];
__device__ int    g_fillpos[E_NUM];
__device__ int    g_perm[SLOTS];
__device__ int    g_tileExpert[MAX_TILES];
__device__ int    g_tilePos[MAX_TILES];
__device__ int    g_tileEnd[MAX_TILES];
__device__ int    g_nTiles;

__device__ __forceinline__ float gelu_exact(float x) {
    return 0.5f * x * (1.0f + erff(x * 0.7071067811865476f));
}

__device__ __forceinline__ uint32_t smem_to_u32(const void* p) {
    uint32_t a;
    asm("{ .reg .u64 t; cvta.to.shared.u64 t, %1; cvt.u32.u64 %0, t; }" : "=r"(a) : "l"(p));
    return a;
}
#define CP_ASYNC16(dst, src, sz) \
    asm volatile("cp.async.cg.shared.global [%0], [%1], 16, %2;" \
                 :: "r"(dst), "l"(src), "r"(sz))
#define CP_COMMIT() asm volatile("cp.async.commit_group;" ::: "memory")
#define CP_WAIT2()  asm volatile("cp.async.wait_group 2;" ::: "memory")

// ---------------- misc small kernels ---------------------------------------
// x -> [xh | xh | xl]  (row stride 3072); block 0 also zeroes g_counts
__global__ void xsplit_kernel(const float* __restrict__ x) {
    if (blockIdx.x == 0 && threadIdx.x < E_NUM) g_counts[threadIdx.x] = 0;
    int i = blockIdx.x * blockDim.x + threadIdx.x;    // over T*D/4
    int t = i >> 8;                                   // D/4 = 256
    int c4 = (i & 255) * 4;
    float4 v = reinterpret_cast<const float4*>(x)[i];
    __half h[4], l[4];
    float vv[4] = {v.x, v.y, v.z, v.w};
#pragma unroll
    for (int q = 0; q < 4; q++) {
        h[q] = __float2half_rn(vv[q]);
        l[q] = __float2half_rn(vv[q] - __half2float(h[q]));
    }
    __half* row = g_xsplit + (size_t)t * KR_DIM + c4;
    __half2 h01 = __halves2half2(h[0], h[1]), h23 = __halves2half2(h[2], h[3]);
    __half2 l01 = __halves2half2(l[0], l[1]), l23 = __halves2half2(l[2], l[3]);
    ((__half2*)(row))[0] = h01;        ((__half2*)(row))[1] = h23;
    ((__half2*)(row + 1024))[0] = h01; ((__half2*)(row + 1024))[1] = h23;
    ((__half2*)(row + 2048))[0] = l01; ((__half2*)(row + 2048))[1] = l23;
}

// Wr1*32 -> [wh | wl | wh]  (row stride 3072)
__global__ void wsplit_kernel(const float* __restrict__ w) {
    int i = blockIdx.x * blockDim.x + threadIdx.x;    // over R*D/4
    int r = i >> 8;
    int c4 = (i & 255) * 4;
    float4 v = reinterpret_cast<const float4*>(w)[i];
    float vv[4] = {v.x * 32.f, v.y * 32.f, v.z * 32.f, v.w * 32.f};
    __half h[4], l[4];
#pragma unroll
    for (int q = 0; q < 4; q++) {
        h[q] = __float2half_rn(vv[q]);
        l[q] = __float2half_rn(vv[q] - __half2float(h[q]));
    }
    __half* row = g_wr1split + (size_t)r * KR_DIM + c4;
    __half2 h01 = __halves2half2(h[0], h[1]), h23 = __halves2half2(h[2], h[3]);
    __half2 l01 = __halves2half2(l[0], l[1]), l23 = __halves2half2(l[2], l[3]);
    ((__half2*)(row))[0] = h01;        ((__half2*)(row))[1] = h23;
    ((__half2*)(row + 1024))[0] = l01; ((__half2*)(row + 1024))[1] = l23;
    ((__half2*)(row + 2048))[0] = h01; ((__half2*)(row + 2048))[1] = h23;
}

// fp32 -> fp16 conversion (4 elems/thread). tag: 1=W1, 2=W2
__global__ void f2h_kernel(const float* __restrict__ src, int n4, int tag) {
    int i = blockIdx.x * blockDim.x + threadIdx.x;
    if (i >= n4) return;
    __half* dst = (tag == 1) ? g_W1h : g_W2h;
    float4 v = reinterpret_cast<const float4*>(src)[i];
    __half2* d2 = reinterpret_cast<__half2*>(dst + (size_t)i * 4);
    d2[0] = __floats2half2_rn(v.x, v.y);
    d2[1] = __floats2half2_rn(v.z, v.w);
}

// ---------------- unified HMMA GEMM -----------------------------------------
// MODE 0: router  h = gelu((1/32)*A'B'^T + br1) -> g_hrouter fp32, M dense
// MODE 1: UP      He = gelu(xh@W1[e]^T + b1[e]) fp16, gathered (token=slot>>1)
// MODE 2: DOWN    Y  = He@W2[e]^T + b2[e] fp32, gathered (slot)
// Tile M=128, N=256, K-chunk 64, 4-stage cp.async, 256 threads.
// Warp grid 2(M) x 4(N), warp tile 64x64 -> minimal LDSM traffic per FLOP.
#define OFF_SLOT   0
#define OFF_STAGE  1024
#define STAGE_BYTES 49152           // A 16KB + B 32KB
#define NSTAGE 4
#define SMEM_TOTAL (OFF_STAGE + NSTAGE * STAGE_BYTES)

template <int MODE>
__global__ void __launch_bounds__(256, 1) moe_gemm_kernel(const float* __restrict__ bias_in)
{
    constexpr int K_DIM = (MODE == 0) ? KR_DIM : (MODE == 1 ? 1024 : 4096);
    constexpr int A_STRIDE = (MODE == 2) ? 4096 : KR_DIM;
    constexpr int NITER = K_DIM / 64;

    extern __shared__ char smem[];
    const uint32_t sb = smem_to_u32(smem);
    int* sSlot = (int*)(smem + OFF_SLOT);
    const int tid = threadIdx.x;
    const int wid = tid >> 5;
    const int lane = tid & 31;
    const int n0 = blockIdx.x * 256;

    int m0 = 0, eIdx = 0;
    if (MODE == 0) {
        m0 = blockIdx.y * 128;
    } else {
        int mt = blockIdx.y;
        if (mt >= g_nTiles) return;
        eIdx = g_tileExpert[mt];
        int pos0 = g_tilePos[mt], segEnd = g_tileEnd[mt];
        if (tid < 128) {
            int p = pos0 + tid;
            sSlot[tid] = (p < segEnd) ? g_perm[p] : -1;
        }
    }
    __syncthreads();

    const __half* Abase = (MODE == 2) ? g_He : g_xsplit;
    const __half* Bbase;
    const float* bptr;
    if (MODE == 0)      { Bbase = g_wr1split;                              bptr = bias_in; }
    else if (MODE == 1) { Bbase = g_W1h + (size_t)eIdx * (H_DIM * D_DIM);  bptr = bias_in + eIdx * H_DIM; }
    else                { Bbase = g_W2h + (size_t)eIdx * (D_DIM * H_DIM);  bptr = bias_in + eIdx * D_DIM; }

    // Per-thread A-gather rows (128 rows x 8 chunks / 256 thr = 4 per thread)
    int aRow[4];
    uint32_t aSz[4];
#pragma unroll
    for (int j = 0; j < 4; j++) {
        int r = (tid + j * 256) >> 3;
        aSz[j] = 16;
        if (MODE == 0) aRow[j] = m0 + r;
        else {
            int slot = sSlot[r];
            if (slot < 0) { aRow[j] = 0; aSz[j] = 0; }
            else aRow[j] = (MODE == 1) ? (slot >> 1) : slot;
        }
    }

    // ---- stage loader (A: 128x128B gathered; B: 256x128B) ----
    auto load_stage = [&](int it) {
        const uint32_t so = sb + OFF_STAGE + (uint32_t)(it & 3) * STAGE_BYTES;
        const int kb = it * 128;  // bytes along K
#pragma unroll
        for (int j = 0; j < 4; j++) {
            int c = tid + j * 256;          // 0..1023
            int r = c >> 3;                 // 0..127
            int kc = (c & 7) << 4;          // 0..112
            uint32_t dst = so + (uint32_t)(r * 128 + (kc ^ ((r & 7) << 4)));
            const char* src = (const char*)(Abase + (size_t)aRow[j] * A_STRIDE) + kb + kc;
            CP_ASYNC16(dst, src, aSz[j]);
        }
#pragma unroll
        for (int j = 0; j < 8; j++) {
            int c = tid + j * 256;          // 0..2047
            int r = c >> 3;                 // 0..255
            int kc = (c & 7) << 4;
            uint32_t dst = so + 16384u + (uint32_t)(r * 128 + (kc ^ ((r & 7) << 4)));
            const char* src = (const char*)(Bbase + (size_t)(n0 + r) * K_DIM) + kb + kc;
            CP_ASYNC16(dst, src, 16u);
        }
    };

    // warp grid: 2 (M) x 4 (N); warp tile 64x64
    const int wm = (wid & 1) * 64;
    const int wn = (wid >> 1) * 64;

    float acc[4][8][4];
#pragma unroll
    for (int i = 0; i < 4; i++)
#pragma unroll
        for (int j = 0; j < 8; j++)
#pragma unroll
            for (int k = 0; k < 4; k++) acc[i][j][k] = 0.f;

    // zero-fill padded A rows in all 4 buffers once
    if (MODE != 0) {
#pragma unroll
        for (int j = 0; j < 4; j++) {
            if (aSz[j] == 0) {
                int c = tid + j * 256;
                int r = c >> 3;
                int kc = (c & 7) << 4;
                uint32_t off = (uint32_t)(r * 128 + (kc ^ ((r & 7) << 4)));
#pragma unroll
                for (int s = 0; s < 4; s++)
                    *(uint4*)(smem + OFF_STAGE + s * STAGE_BYTES + off) =
                        make_uint4(0u, 0u, 0u, 0u);
            }
        }
        __syncthreads();
    }
#pragma unroll
    for (int p = 0; p < 3; p++) {
        load_stage(p);
        CP_COMMIT();
    }

    for (int it = 0; it < NITER; ++it) {
        CP_WAIT2();                   // stage `it` resident
        __syncthreads();              // all warps done with compute(it-1)
        if (it + 3 < NITER) load_stage(it + 3);   // refills buffer (it-1)&3
        CP_COMMIT();                  // keep group count constant

        const uint32_t aOff = sb + OFF_STAGE + (uint32_t)(it & 3) * STAGE_BYTES;
        const uint32_t bOff = aOff + 16384u;

#pragma unroll
        for (int ks = 0; ks < 4; ks++) {
            const int kb32 = ks * 32;
            uint32_t af[4][4];
#pragma unroll
            for (int mf = 0; mf < 4; mf++) {
                int r = wm + mf * 16 + (lane & 15);
                int col = kb32 + ((lane >> 4) << 4);
                uint32_t a = aOff + (uint32_t)(r * 128 + (col ^ ((r & 7) << 4)));
                asm volatile(
                    "ldmatrix.sync.aligned.m8n8.x4.shared.b16 {%0,%1,%2,%3}, [%4];"
                    : "=r"(af[mf][0]), "=r"(af[mf][1]), "=r"(af[mf][2]), "=r"(af[mf][3])
                    : "r"(a));
            }
            uint32_t bf[8][2];
#pragma unroll
            for (int np = 0; np < 4; np++) {
                int r = wn + np * 16 + ((lane >> 4) << 3) + (lane & 7);
                int col = kb32 + ((lane >> 3) & 1) * 16;
                uint32_t a = bOff + (uint32_t)(r * 128 + (col ^ ((r & 7) << 4)));
                asm volatile(
                    "ldmatrix.sync.aligned.m8n8.x4.shared.b16 {%0,%1,%2,%3}, [%4];"
                    : "=r"(bf[2 * np][0]), "=r"(bf[2 * np][1]),
                      "=r"(bf[2 * np + 1][0]), "=r"(bf[2 * np + 1][1])
                    : "r"(a));
            }
#pragma unroll
            for (int mf = 0; mf < 4; mf++)
#pragma unroll
                for (int nf = 0; nf < 8; nf++) {
                    asm volatile(
                        "mma.sync.aligned.m16n8k16.row.col.f32.f16.f16.f32 "
                        "{%0,%1,%2,%3}, {%4,%5,%6,%7}, {%8,%9}, {%0,%1,%2,%3};"
                        : "+f"(acc[mf][nf][0]), "+f"(acc[mf][nf][1]),
                          "+f"(acc[mf][nf][2]), "+f"(acc[mf][nf][3])
                        : "r"(af[mf][0]), "r"(af[mf][1]), "r"(af[mf][2]), "r"(af[mf][3]),
                          "r"(bf[nf][0]), "r"(bf[nf][1]));
                }
        }
    }

    // ---- epilogue ----
    const int lr = lane >> 2;
    const int lc = (lane & 3) * 2;
#pragma unroll
    for (int mf = 0; mf < 4; mf++) {
#pragma unroll
        for (int h = 0; h < 2; h++) {
            int rl = wm + mf * 16 + lr + h * 8;
            int orow;
            if (MODE == 0) orow = m0 + rl;
            else {
                int slot = sSlot[rl];
                if (slot < 0) continue;
                orow = slot;
            }
#pragma unroll
            for (int nf = 0; nf < 8; nf++) {
                int col = n0 + wn + nf * 8 + lc;
                float v0 = acc[mf][nf][h * 2 + 0];
                float v1 = acc[mf][nf][h * 2 + 1];
                if (MODE == 0) {
                    v0 = gelu_exact(v0 * 0.03125f + bptr[col]);
                    v1 = gelu_exact(v1 * 0.03125f + bptr[col + 1]);
                    *reinterpret_cast<float2*>(&g_hrouter[(size_t)orow * R_DIM + col]) =
                        make_float2(v0, v1);
                } else if (MODE == 1) {
                    v0 = gelu_exact(v0 + bptr[col]);
                    v1 = gelu_exact(v1 + bptr[col + 1]);
                    *reinterpret_cast<__half2*>(&g_He[(size_t)orow * H_DIM + col]) =
                        __floats2half2_rn(v0, v1);
                } else {
                    *reinterpret_cast<float2*>(&g_Y[(size_t)orow * D_DIM + col]) =
                        make_float2(v0 + bptr[col], v1 + bptr[col + 1]);
                }
            }
        }
    }
}

// ---------------- router stage 2: logits, softmax, top-2 -------------------
__global__ void router_topk_kernel(const float* __restrict__ Wr2,  // [8,512]
                                   const float* __restrict__ br2)  // [8]
{
    int warp = threadIdx.x >> 5;
    int lane = threadIdx.x & 31;
    int t = blockIdx.x * 8 + warp;
    const float* h = g_hrouter + (size_t)t * R_DIM;

    float acc[E_NUM];
#pragma unroll
    for (int e = 0; e < E_NUM; e++) acc[e] = 0.f;
#pragma unroll
    for (int j = 0; j < 16; j++) {
        int i = lane + 32 * j;
        float hv = h[i];
#pragma unroll
        for (int e = 0; e < E_NUM; e++) acc[e] += hv * Wr2[e * R_DIM + i];
    }
#pragma unroll
    for (int off = 16; off > 0; off >>= 1)
#pragma unroll
        for (int e = 0; e < E_NUM; e++)
            acc[e] += __shfl_xor_sync(0xffffffffu, acc[e], off);

    if (lane == 0) {
        float l[E_NUM];
#pragma unroll
        for (int e = 0; e < E_NUM; e++) l[e] = acc[e] + br2[e];
        int i0 = 0; float v0 = l[0];
#pragma unroll
        for (int e = 1; e < E_NUM; e++) if (l[e] > v0) { v0 = l[e]; i0 = e; }
        int i1 = -1; float v1 = -1e30f;
#pragma unroll
        for (int e = 0; e < E_NUM; e++) if (e != i0 && l[e] > v1) { v1 = l[e]; i1 = e; }
        float m = v0;
        float s = 0.f;
#pragma unroll
        for (int e = 0; e < E_NUM; e++) s += expf(l[e] - m);
        float w0 = expf(v0 - m) / s;
        float w1 = expf(v1 - m) / s;
        g_expIdx[2 * t] = i0;     g_expIdx[2 * t + 1] = i1;
        g_expW[2 * t] = w0;       g_expW[2 * t + 1] = w1;
        atomicAdd(&g_counts[i0], 1);
        atomicAdd(&g_counts[i1], 1);
    }
}

// ---------------- scan + tile map (single thread) ---------------------------
__global__ void scan_kernel() {
    int off = 0, nt = 0;
    for (int e = 0; e < E_NUM; e++) {
        int cnt = g_counts[e];
        g_fillpos[e] = off;
        int tiles = (cnt + 127) >> 7;
        for (int j = 0; j < tiles; j++) {
            g_tileExpert[nt] = e;
            g_tilePos[nt] = off + j * 128;
            g_tileEnd[nt] = off + cnt;
            nt++;
        }
        off += cnt;
    }
    g_nTiles = nt;
}

__global__ void fill_kernel() {
    int s = blockIdx.x * blockDim.x + threadIdx.x;
    if (s >= SLOTS) return;
    int e = g_expIdx[s];
    int pos = atomicAdd(&g_fillpos[e], 1);
    g_perm[pos] = s;
}

// ---------------- combine: out = w0*Y[2t] + w1*Y[2t+1] ---------------------
__global__ void combine_kernel(float* __restrict__ out) {
    int i = blockIdx.x * blockDim.x + threadIdx.x;  // over T*D/4
    int t = i >> 8;
    int c = i & 255;
    float w0 = g_expW[2 * t];
    float w1 = g_expW[2 * t + 1];
    const float4* Y4 = reinterpret_cast<const float4*>(g_Y);
    float4 y0 = Y4[(size_t)(2 * t) * 256 + c];
    float4 y1 = Y4[(size_t)(2 * t + 1) * 256 + c];
    float4 r;
    r.x = w0 * y0.x + w1 * y1.x;
    r.y = w0 * y0.y + w1 * y1.y;
    r.z = w0 * y0.z + w1 * y1.z;
    r.w = w0 * y0.w + w1 * y1.w;
    reinterpret_cast<float4*>(out)[i] = r;
}

// ---------------- launch ----------------------------------------------------
extern "C" void kernel_launch(void* const* d_in, const int* in_sizes, int n_in,
                              void* d_out, int out_size) {
    const float* x   = (const float*)d_in[0];
    const float* Wr1 = (const float*)d_in[1];
    const float* br1 = (const float*)d_in[2];
    const float* Wr2 = (const float*)d_in[3];
    const float* br2 = (const float*)d_in[4];
    const float* W1  = (const float*)d_in[5];
    const float* b1  = (const float*)d_in[6];
    const float* W2  = (const float*)d_in[7];
    const float* b2  = (const float*)d_in[8];
    float* out = (float*)d_out;

    // One-time stream/event setup (no device memory; identical work each call)
    static cudaStream_t sW = nullptr;
    static cudaEvent_t evFork = nullptr, evW = nullptr;
    if (sW == nullptr) {
        cudaStreamCreateWithFlags(&sW, cudaStreamNonBlocking);
        cudaEventCreateWithFlags(&evFork, cudaEventDisableTiming);
        cudaEventCreateWithFlags(&evW, cudaEventDisableTiming);
        cudaFuncSetAttribute(moe_gemm_kernel<0>, cudaFuncAttributeMaxDynamicSharedMemorySize, SMEM_TOTAL);
        cudaFuncSetAttribute(moe_gemm_kernel<1>, cudaFuncAttributeMaxDynamicSharedMemorySize, SMEM_TOTAL);
        cudaFuncSetAttribute(moe_gemm_kernel<2>, cudaFuncAttributeMaxDynamicSharedMemorySize, SMEM_TOTAL);
    }

    // Fork: weight conversions run concurrently with the router chain
    cudaEventRecord(evFork, 0);
    cudaStreamWaitEvent(sW, evFork, 0);
    {
        int n4 = E_NUM * H_DIM * D_DIM / 4;
        f2h_kernel<<<n4 / 256, 256, 0, sW>>>(W1, n4, 1);
        f2h_kernel<<<n4 / 256, 256, 0, sW>>>(W2, n4, 2);
    }
    cudaEventRecord(evW, sW);

    // Router chain on the main stream
    xsplit_kernel<<<(T_TOKENS * D_DIM / 4) / 256, 256>>>(x);
    wsplit_kernel<<<(R_DIM * D_DIM / 4) / 256, 256>>>(Wr1);
    moe_gemm_kernel<0><<<dim3(2, 64), 256, SMEM_TOTAL>>>(br1);
    router_topk_kernel<<<T_TOKENS / 8, 256>>>(Wr2, br2);
    scan_kernel<<<1, 1>>>();
    fill_kernel<<<SLOTS / 256, 256>>>();

    // Join: expert GEMMs need converted weights + routing
    cudaStreamWaitEvent(0, evW, 0);
    moe_gemm_kernel<1><<<dim3(H_DIM / 256, MAX_TILES), 256, SMEM_TOTAL>>>(b1);
    moe_gemm_kernel<2><<<dim3(D_DIM / 256, MAX_TILES), 256, SMEM_TOTAL>>>(b2);

    combine_kernel<<<T_TOKENS * D_DIM / 4 / 256, 256>>>(out);
}

// round 6
// speedup vs baseline: 1.0342x; 1.0342x over previous
#include <cuda_runtime.h>
#include <cuda_fp16.h>
#include <math.h>
#include <stdint.h>

// Problem constants
#define T_TOKENS 8192
#define D_DIM    1024
#define H_DIM    4096
#define R_DIM    512
#define E_NUM    8
#define SLOTS    (T_TOKENS * 2)
#define MAX_TILES 136
#define KR_DIM   3072   // router split-K: [xh|xh|xl] x [wh|wl|wh]

// ---------------- scratch (device globals; no allocation allowed) ----------
__device__ __half g_xsplit[T_TOKENS * KR_DIM];       // [xh|xh|xl]      50MB
__device__ __half g_wr1split[R_DIM * KR_DIM];        // [wh|wl|wh]*32    3MB
__device__ __half g_W1h[E_NUM * H_DIM * D_DIM];      // W1 fp16         67MB
__device__ __half g_W2h[E_NUM * D_DIM * H_DIM];      // W2 fp16         67MB
__device__ float  g_hrouter[T_TOKENS * R_DIM];       // gelu(x@Wr1^T+br1)
__device__ __half g_He[SLOTS * H_DIM];               // expert hidden  134MB
__device__ float  g_Y[2 * SLOTS * D_DIM];            // K-split partials 134MB
__device__ int    g_expIdx[SLOTS];
__device__ float  g_expW[SLOTS];
__device__ int    g_counts[E_NUM];
__device__ int    g_fillpos[E_NUM];
__device__ int    g_perm[SLOTS];

__device__ __forceinline__ float gelu_exact(float x) {
    return 0.5f * x * (1.0f + erff(x * 0.7071067811865476f));
}

__device__ __forceinline__ uint32_t smem_to_u32(const void* p) {
    uint32_t a;
    asm("{ .reg .u64 t; cvta.to.shared.u64 t, %1; cvt.u32.u64 %0, t; }" : "=r"(a) : "l"(p));
    return a;
}
#define CP_ASYNC16(dst, src, sz) \
    asm volatile("cp.async.cg.shared.global [%0], [%1], 16, %2;" \
                 :: "r"(dst), "l"(src), "r"(sz))
#define CP_COMMIT() asm volatile("cp.async.commit_group;" ::: "memory")
#define CP_WAIT0()  asm volatile("cp.async.wait_group 0;" ::: "memory")

// ---------------- fused converts --------------------------------------------
// W1 and W2 fp32->fp16 in one launch. i in [0, 2*n4)
__global__ void conv_kernel(const float* __restrict__ W1,
                            const float* __restrict__ W2, int n4) {
    int i = blockIdx.x * blockDim.x + threadIdx.x;
    const float* src;
    __half* dst;
    if (i < n4) { src = W1; dst = g_W1h; }
    else        { i -= n4; src = W2; dst = g_W2h; }
    float4 v = reinterpret_cast<const float4*>(src)[i];
    __half2* d2 = reinterpret_cast<__half2*>(dst + (size_t)i * 4);
    d2[0] = __floats2half2_rn(v.x, v.y);
    d2[1] = __floats2half2_rn(v.z, v.w);
}

// x -> [xh|xh|xl] and Wr1*32 -> [wh|wl|wh]; block0 zeroes counts/fillpos
__global__ void split_kernel(const float* __restrict__ x,
                             const float* __restrict__ w) {
    if (blockIdx.x == 0 && threadIdx.x < 2 * E_NUM) {
        if (threadIdx.x < E_NUM) g_counts[threadIdx.x] = 0;
        else g_fillpos[threadIdx.x - E_NUM] = 0;
    }
    int i = blockIdx.x * blockDim.x + threadIdx.x;
    int row = i >> 8;                 // 256 quads per 1024-elem row
    int c4 = (i & 255) * 4;
    __half h[4], l[4];
    if (row < T_TOKENS) {
        float4 v = reinterpret_cast<const float4*>(x)[i];
        float vv[4] = {v.x, v.y, v.z, v.w};
#pragma unroll
        for (int q = 0; q < 4; q++) {
            h[q] = __float2half_rn(vv[q]);
            l[q] = __float2half_rn(vv[q] - __half2float(h[q]));
        }
        __half* r = g_xsplit + (size_t)row * KR_DIM + c4;
        __half2 h01 = __halves2half2(h[0], h[1]), h23 = __halves2half2(h[2], h[3]);
        __half2 l01 = __halves2half2(l[0], l[1]), l23 = __halves2half2(l[2], l[3]);
        ((__half2*)(r))[0] = h01;        ((__half2*)(r))[1] = h23;
        ((__half2*)(r + 1024))[0] = h01; ((__half2*)(r + 1024))[1] = h23;
        ((__half2*)(r + 2048))[0] = l01; ((__half2*)(r + 2048))[1] = l23;
    } else {
        int wr = row - T_TOKENS;     // 0..511
        float4 v = reinterpret_cast<const float4*>(w)[(size_t)wr * 256 + (c4 >> 2)];
        float vv[4] = {v.x * 32.f, v.y * 32.f, v.z * 32.f, v.w * 32.f};
#pragma unroll
        for (int q = 0; q < 4; q++) {
            h[q] = __float2half_rn(vv[q]);
            l[q] = __float2half_rn(vv[q] - __half2float(h[q]));
        }
        __half* r = g_wr1split + (size_t)wr * KR_DIM + c4;
        __half2 h01 = __halves2half2(h[0], h[1]), h23 = __halves2half2(h[2], h[3]);
        __half2 l01 = __halves2half2(l[0], l[1]), l23 = __halves2half2(l[2], l[3]);
        ((__half2*)(r))[0] = h01;        ((__half2*)(r))[1] = h23;
        ((__half2*)(r + 1024))[0] = l01; ((__half2*)(r + 1024))[1] = l23;
        ((__half2*)(r + 2048))[0] = h01; ((__half2*)(r + 2048))[1] = h23;
    }
}

// ---------------- unified HMMA GEMM -----------------------------------------
// MODE 0: router  h = gelu((1/32)*A'B'^T + br1) -> g_hrouter fp32, M dense
// MODE 1: UP      He = gelu(xh@W1[e]^T + b1[e]) fp16, gathered (token=slot>>1)
// MODE 2: DOWN    Ypart = He@W2[e]^T (+b2 on z=0), gathered, K split by z
// Tile M=128, N=256, K-chunk 128 (256B rows), 2-stage cp.async, 256 threads.
#define OFF_STAGE  1024
#define STAGE_BYTES 98304           // A 32KB + B 64KB
#define SMEM_TOTAL (OFF_STAGE + 2 * STAGE_BYTES)

template <int MODE>
__global__ void __launch_bounds__(256, 1) moe_gemm_kernel(const float* __restrict__ bias_in)
{
    constexpr int K_DIM = (MODE == 0) ? KR_DIM : (MODE == 1 ? 1024 : 4096);
    constexpr int A_STRIDE = (MODE == 2) ? 4096 : KR_DIM;
    constexpr int K_LOCAL = (MODE == 2) ? 2048 : K_DIM;
    constexpr int N2 = K_LOCAL / 128;

    extern __shared__ char smem[];
    const uint32_t sb = smem_to_u32(smem);
    int* sSlot = (int*)smem;
    const int tid = threadIdx.x;
    const int wid = tid >> 5;
    const int lane = tid & 31;
    const int n0 = blockIdx.x * 256;
    const int kz = (MODE == 2) ? blockIdx.z : 0;
    const size_t kBase = (size_t)kz * 2048 * 2;   // bytes along K

    int m0 = 0, eIdx = 0;
    if (MODE == 0) {
        m0 = blockIdx.y * 128;
    } else {
        // replay the 8-expert tile map from g_counts (no scan kernel)
        int mt = blockIdx.y;
        eIdx = -1;
        int pos0 = 0, segEnd = 0;
        int tS = 0, off = 0;
#pragma unroll
        for (int e = 0; e < E_NUM; e++) {
            int cnt = g_counts[e];
            int tiles = (cnt + 127) >> 7;
            if (eIdx < 0 && mt >= tS && mt < tS + tiles) {
                eIdx = e;
                pos0 = off + (mt - tS) * 128;
                segEnd = off + cnt;
            }
            tS += tiles;
            off += cnt;
        }
        if (eIdx < 0) return;
        if (tid < 128) {
            int p = pos0 + tid;
            sSlot[tid] = (p < segEnd) ? g_perm[p] : -1;
        }
    }
    __syncthreads();

    const __half* Abase = (MODE == 2) ? g_He : g_xsplit;
    const __half* Bbase;
    const float* bptr;
    if (MODE == 0)      { Bbase = g_wr1split;                              bptr = bias_in; }
    else if (MODE == 1) { Bbase = g_W1h + (size_t)eIdx * (H_DIM * D_DIM);  bptr = bias_in + eIdx * H_DIM; }
    else                { Bbase = g_W2h + (size_t)eIdx * (D_DIM * H_DIM);  bptr = bias_in + eIdx * D_DIM; }

    // Per-thread A-gather rows: 128 rows x 16 chunks / 256 thr = 8 per thread
    int aRow[8];
    uint32_t aSz[8];
#pragma unroll
    for (int j = 0; j < 8; j++) {
        int r = (tid + j * 256) >> 4;
        aSz[j] = 16;
        if (MODE == 0) aRow[j] = m0 + r;
        else {
            int slot = sSlot[r];
            if (slot < 0) { aRow[j] = 0; aSz[j] = 0; }   // sz=0 -> cp.async zero-fills
            else aRow[j] = (MODE == 1) ? (slot >> 1) : slot;
        }
    }

    // ---- stage loader (A: 128 rows x 256B gathered; B: 256 rows x 256B) ----
    auto load_stage = [&](int it) {
        const uint32_t so = sb + OFF_STAGE + (uint32_t)(it & 1) * STAGE_BYTES;
        const size_t kb = kBase + (size_t)it * 256;
#pragma unroll
        for (int j = 0; j < 8; j++) {
            int c = tid + j * 256;          // 0..2047
            int r = c >> 4;                 // 0..127
            int kc = (c & 15) << 4;         // 0..240
            uint32_t dst = so + (uint32_t)(r * 256 + (kc & 128) +
                                           ((kc & 127) ^ ((r & 7) << 4)));
            const char* src = (const char*)(Abase + (size_t)aRow[j] * A_STRIDE) + kb + kc;
            CP_ASYNC16(dst, src, aSz[j]);
        }
#pragma unroll
        for (int j = 0; j < 16; j++) {
            int c = tid + j * 256;          // 0..4095
            int r = c >> 4;                 // 0..255
            int kc = (c & 15) << 4;
            uint32_t dst = so + 32768u + (uint32_t)(r * 256 + (kc & 128) +
                                                    ((kc & 127) ^ ((r & 7) << 4)));
            const char* src = (const char*)(Bbase + (size_t)(n0 + r) * K_DIM) + kb + kc;
            CP_ASYNC16(dst, src, 16u);
        }
    };

    // warp grid: 2 (M) x 4 (N); warp tile 64x64
    const int wm = (wid & 1) * 64;
    const int wn = (wid >> 1) * 64;

    float acc[4][8][4];
#pragma unroll
    for (int i = 0; i < 4; i++)
#pragma unroll
        for (int j = 0; j < 8; j++)
#pragma unroll
            for (int k = 0; k < 4; k++) acc[i][j][k] = 0.f;

    load_stage(0);
    CP_COMMIT();

    for (int it = 0; it < N2; ++it) {
        CP_WAIT0();                   // stage `it` complete (this thread's groups)
        __syncthreads();              // everyone's loads visible; compute(it-1) done
        if (it + 1 < N2) { load_stage(it + 1); CP_COMMIT(); }

        const uint32_t aOff = sb + OFF_STAGE + (uint32_t)(it & 1) * STAGE_BYTES;
        const uint32_t bOff = aOff + 32768u;

#pragma unroll
        for (int ks = 0; ks < 8; ks++) {
            const int kb32 = ks * 32;   // byte offset along 256B row
            uint32_t af[4][4];
#pragma unroll
            for (int mf = 0; mf < 4; mf++) {
                int r = wm + mf * 16 + (lane & 15);
                int col = kb32 + ((lane >> 4) << 4);
                uint32_t a = aOff + (uint32_t)(r * 256 + (col & 128) +
                                               ((col & 127) ^ ((r & 7) << 4)));
                asm volatile(
                    "ldmatrix.sync.aligned.m8n8.x4.shared.b16 {%0,%1,%2,%3}, [%4];"
                    : "=r"(af[mf][0]), "=r"(af[mf][1]), "=r"(af[mf][2]), "=r"(af[mf][3])
                    : "r"(a));
            }
            uint32_t bf[8][2];
#pragma unroll
            for (int np = 0; np < 4; np++) {
                int r = wn + np * 16 + ((lane >> 4) << 3) + (lane & 7);
                int col = kb32 + ((lane >> 3) & 1) * 16;
                uint32_t a = bOff + (uint32_t)(r * 256 + (col & 128) +
                                               ((col & 127) ^ ((r & 7) << 4)));
                asm volatile(
                    "ldmatrix.sync.aligned.m8n8.x4.shared.b16 {%0,%1,%2,%3}, [%4];"
                    : "=r"(bf[2 * np][0]), "=r"(bf[2 * np][1]),
                      "=r"(bf[2 * np + 1][0]), "=r"(bf[2 * np + 1][1])
                    : "r"(a));
            }
#pragma unroll
            for (int mf = 0; mf < 4; mf++)
#pragma unroll
                for (int nf = 0; nf < 8; nf++) {
                    asm volatile(
                        "mma.sync.aligned.m16n8k16.row.col.f32.f16.f16.f32 "
                        "{%0,%1,%2,%3}, {%4,%5,%6,%7}, {%8,%9}, {%0,%1,%2,%3};"
                        : "+f"(acc[mf][nf][0]), "+f"(acc[mf][nf][1]),
                          "+f"(acc[mf][nf][2]), "+f"(acc[mf][nf][3])
                        : "r"(af[mf][0]), "r"(af[mf][1]), "r"(af[mf][2]), "r"(af[mf][3]),
                          "r"(bf[nf][0]), "r"(bf[nf][1]));
                }
        }
    }

    // ---- epilogue ----
    const int lr = lane >> 2;
    const int lc = (lane & 3) * 2;
    float* ybase = g_Y + (size_t)kz * (SLOTS * D_DIM);
    const bool addB = (MODE != 2) || (kz == 0);
#pragma unroll
    for (int mf = 0; mf < 4; mf++) {
#pragma unroll
        for (int h = 0; h < 2; h++) {
            int rl = wm + mf * 16 + lr + h * 8;
            int orow;
            if (MODE == 0) orow = m0 + rl;
            else {
                int slot = sSlot[rl];
                if (slot < 0) continue;
                orow = slot;
            }
#pragma unroll
            for (int nf = 0; nf < 8; nf++) {
                int col = n0 + wn + nf * 8 + lc;
                float v0 = acc[mf][nf][h * 2 + 0];
                float v1 = acc[mf][nf][h * 2 + 1];
                if (MODE == 0) {
                    v0 = gelu_exact(v0 * 0.03125f + bptr[col]);
                    v1 = gelu_exact(v1 * 0.03125f + bptr[col + 1]);
                    *reinterpret_cast<float2*>(&g_hrouter[(size_t)orow * R_DIM + col]) =
                        make_float2(v0, v1);
                } else if (MODE == 1) {
                    v0 = gelu_exact(v0 + bptr[col]);
                    v1 = gelu_exact(v1 + bptr[col + 1]);
                    *reinterpret_cast<__half2*>(&g_He[(size_t)orow * H_DIM + col]) =
                        __floats2half2_rn(v0, v1);
                } else {
                    if (addB) { v0 += bptr[col]; v1 += bptr[col + 1]; }
                    *reinterpret_cast<float2*>(&ybase[(size_t)orow * D_DIM + col]) =
                        make_float2(v0, v1);
                }
            }
        }
    }
}

// ---------------- router stage 2: logits, softmax, top-2 -------------------
__global__ void router_topk_kernel(const float* __restrict__ Wr2,  // [8,512]
                                   const float* __restrict__ br2)  // [8]
{
    int warp = threadIdx.x >> 5;
    int lane = threadIdx.x & 31;
    int t = blockIdx.x * 8 + warp;
    const float* h = g_hrouter + (size_t)t * R_DIM;

    float acc[E_NUM];
#pragma unroll
    for (int e = 0; e < E_NUM; e++) acc[e] = 0.f;
#pragma unroll
    for (int j = 0; j < 16; j++) {
        int i = lane + 32 * j;
        float hv = h[i];
#pragma unroll
        for (int e = 0; e < E_NUM; e++) acc[e] += hv * Wr2[e * R_DIM + i];
    }
#pragma unroll
    for (int off = 16; off > 0; off >>= 1)
#pragma unroll
        for (int e = 0; e < E_NUM; e++)
            acc[e] += __shfl_xor_sync(0xffffffffu, acc[e], off);

    if (lane == 0) {
        float l[E_NUM];
#pragma unroll
        for (int e = 0; e < E_NUM; e++) l[e] = acc[e] + br2[e];
        int i0 = 0; float v0 = l[0];
#pragma unroll
        for (int e = 1; e < E_NUM; e++) if (l[e] > v0) { v0 = l[e]; i0 = e; }
        int i1 = -1; float v1 = -1e30f;
#pragma unroll
        for (int e = 0; e < E_NUM; e++) if (e != i0 && l[e] > v1) { v1 = l[e]; i1 = e; }
        float m = v0;
        float s = 0.f;
#pragma unroll
        for (int e = 0; e < E_NUM; e++) s += expf(l[e] - m);
        float w0 = expf(v0 - m) / s;
        float w1 = expf(v1 - m) / s;
        g_expIdx[2 * t] = i0;     g_expIdx[2 * t + 1] = i1;
        g_expW[2 * t] = w0;       g_expW[2 * t + 1] = w1;
        atomicAdd(&g_counts[i0], 1);
        atomicAdd(&g_counts[i1], 1);
    }
}

// ---------------- fill: segment offsets derived in-register ----------------
__global__ void fill_kernel() {
    int s = blockIdx.x * blockDim.x + threadIdx.x;
    if (s >= SLOTS) return;
    int e = g_expIdx[s];
    int offs = 0;
#pragma unroll
    for (int q = 0; q < E_NUM; q++) {
        int c = g_counts[q];
        if (q < e) offs += c;
    }
    int rank = atomicAdd(&g_fillpos[e], 1);
    g_perm[offs + rank] = s;
}

// ---------------- combine: out = w0*(Ya+Yb)[2t] + w1*(Ya+Yb)[2t+1] ---------
__global__ void combine_kernel(float* __restrict__ out) {
    int i = blockIdx.x * blockDim.x + threadIdx.x;  // over T*D/4
    int t = i >> 8;
    int c = i & 255;
    float w0 = g_expW[2 * t];
    float w1 = g_expW[2 * t + 1];
    const float4* Ya = reinterpret_cast<const float4*>(g_Y);
    const float4* Yb = Ya + (size_t)SLOTS * D_DIM / 4;
    float4 a0 = Ya[(size_t)(2 * t) * 256 + c];
    float4 b0 = Yb[(size_t)(2 * t) * 256 + c];
    float4 a1 = Ya[(size_t)(2 * t + 1) * 256 + c];
    float4 b1 = Yb[(size_t)(2 * t + 1) * 256 + c];
    float4 r;
    r.x = w0 * (a0.x + b0.x) + w1 * (a1.x + b1.x);
    r.y = w0 * (a0.y + b0.y) + w1 * (a1.y + b1.y);
    r.z = w0 * (a0.z + b0.z) + w1 * (a1.z + b1.z);
    r.w = w0 * (a0.w + b0.w) + w1 * (a1.w + b1.w);
    reinterpret_cast<float4*>(out)[i] = r;
}

// ---------------- launch ----------------------------------------------------
extern "C" void kernel_launch(void* const* d_in, const int* in_sizes, int n_in,
                              void* d_out, int out_size) {
    const float* x   = (const float*)d_in[0];
    const float* Wr1 = (const float*)d_in[1];
    const float* br1 = (const float*)d_in[2];
    const float* Wr2 = (const float*)d_in[3];
    const float* br2 = (const float*)d_in[4];
    const float* W1  = (const float*)d_in[5];
    const float* b1  = (const float*)d_in[6];
    const float* W2  = (const float*)d_in[7];
    const float* b2  = (const float*)d_in[8];
    float* out = (float*)d_out;

    static cudaStream_t sW = nullptr;
    static cudaEvent_t evFork = nullptr, evW = nullptr;
    if (sW == nullptr) {
        cudaStreamCreateWithFlags(&sW, cudaStreamNonBlocking);
        cudaEventCreateWithFlags(&evFork, cudaEventDisableTiming);
        cudaEventCreateWithFlags(&evW, cudaEventDisableTiming);
        cudaFuncSetAttribute(moe_gemm_kernel<0>, cudaFuncAttributeMaxDynamicSharedMemorySize, SMEM_TOTAL);
        cudaFuncSetAttribute(moe_gemm_kernel<1>, cudaFuncAttributeMaxDynamicSharedMemorySize, SMEM_TOTAL);
        cudaFuncSetAttribute(moe_gemm_kernel<2>, cudaFuncAttributeMaxDynamicSharedMemorySize, SMEM_TOTAL);
    }

    // Fork: W1/W2 conversion concurrent with router chain
    cudaEventRecord(evFork, 0);
    cudaStreamWaitEvent(sW, evFork, 0);
    {
        int n4 = E_NUM * H_DIM * D_DIM / 4;
        conv_kernel<<<2 * n4 / 256, 256, 0, sW>>>(W1, W2, n4);
    }
    cudaEventRecord(evW, sW);

    // Router chain
    split_kernel<<<((T_TOKENS + R_DIM) * 256) / 256, 256>>>(x, Wr1);
    moe_gemm_kernel<0><<<dim3(2, 64, 1), 256, SMEM_TOTAL>>>(br1);
    router_topk_kernel<<<T_TOKENS / 8, 256>>>(Wr2, br2);
    fill_kernel<<<SLOTS / 256, 256>>>();

    // Experts
    cudaStreamWaitEvent(0, evW, 0);
    moe_gemm_kernel<1><<<dim3(H_DIM / 256, MAX_TILES, 1), 256, SMEM_TOTAL>>>(b1);
    moe_gemm_kernel<2><<<dim3(D_DIM / 256, MAX_TILES, 2), 256, SMEM_TOTAL>>>(b2);

    combine_kernel<<<T_TOKENS * D_DIM / 4 / 256, 256>>>(out);
}

// round 7
// speedup vs baseline: 1.0777x; 1.0420x over previous
#include <cuda_runtime.h>
#include <cuda_fp16.h>
#include <math.h>
#include <stdint.h>

// Problem constants
#define T_TOKENS 8192
#define D_DIM    1024
#define H_DIM    4096
#define R_DIM    512
#define E_NUM    8
#define SLOTS    (T_TOKENS * 2)
#define MAX_TILES 136
#define KR_DIM   3072   // router split-K: [xh|xh|xl] x [wh|wl|wh]

// ---------------- scratch (device globals; no allocation allowed) ----------
__device__ __half g_xsplit[T_TOKENS * KR_DIM];       // [xh|xh|xl]      50MB
__device__ __half g_wr1split[R_DIM * KR_DIM];        // [wh|wl|wh]*32    3MB
__device__ __half g_W1h[E_NUM * H_DIM * D_DIM];      // W1 fp16         67MB
__device__ __half g_W2h[E_NUM * D_DIM * H_DIM];      // W2 fp16         67MB
__device__ float  g_hrouter[T_TOKENS * R_DIM];       // gelu(x@Wr1^T+br1)
__device__ __half g_He[SLOTS * H_DIM];               // expert hidden  134MB
__device__ float  g_Y[2 * SLOTS * D_DIM];            // K-split partials 134MB
__device__ int    g_expIdx[SLOTS];
__device__ float  g_expW[SLOTS];
__device__ int    g_counts[E_NUM];
__device__ int    g_fillpos[E_NUM];
__device__ int    g_perm[SLOTS];

__device__ __forceinline__ float gelu_exact(float x) {
    return 0.5f * x * (1.0f + erff(x * 0.7071067811865476f));
}

__device__ __forceinline__ uint32_t smem_to_u32(const void* p) {
    uint32_t a;
    asm("{ .reg .u64 t; cvta.to.shared.u64 t, %1; cvt.u32.u64 %0, t; }" : "=r"(a) : "l"(p));
    return a;
}
#define CP_ASYNC16(dst, src, sz) \
    asm volatile("cp.async.cg.shared.global [%0], [%1], 16, %2;" \
                 :: "r"(dst), "l"(src), "r"(sz))
#define CP_COMMIT() asm volatile("cp.async.commit_group;" ::: "memory")
#define CP_WAIT1()  asm volatile("cp.async.wait_group 1;" ::: "memory")

// ---------------- fused converts --------------------------------------------
__global__ void conv_kernel(const float* __restrict__ W1,
                            const float* __restrict__ W2, int n4) {
    int i = blockIdx.x * blockDim.x + threadIdx.x;
    const float* src;
    __half* dst;
    if (i < n4) { src = W1; dst = g_W1h; }
    else        { i -= n4; src = W2; dst = g_W2h; }
    float4 v = reinterpret_cast<const float4*>(src)[i];
    __half2* d2 = reinterpret_cast<__half2*>(dst + (size_t)i * 4);
    d2[0] = __floats2half2_rn(v.x, v.y);
    d2[1] = __floats2half2_rn(v.z, v.w);
}

// x -> [xh|xh|xl] and Wr1*32 -> [wh|wl|wh]; block0 zeroes counts/fillpos
__global__ void split_kernel(const float* __restrict__ x,
                             const float* __restrict__ w) {
    if (blockIdx.x == 0 && threadIdx.x < 2 * E_NUM) {
        if (threadIdx.x < E_NUM) g_counts[threadIdx.x] = 0;
        else g_fillpos[threadIdx.x - E_NUM] = 0;
    }
    int i = blockIdx.x * blockDim.x + threadIdx.x;
    int row = i >> 8;
    int c4 = (i & 255) * 4;
    __half h[4], l[4];
    if (row < T_TOKENS) {
        float4 v = reinterpret_cast<const float4*>(x)[i];
        float vv[4] = {v.x, v.y, v.z, v.w};
#pragma unroll
        for (int q = 0; q < 4; q++) {
            h[q] = __float2half_rn(vv[q]);
            l[q] = __float2half_rn(vv[q] - __half2float(h[q]));
        }
        __half* r = g_xsplit + (size_t)row * KR_DIM + c4;
        __half2 h01 = __halves2half2(h[0], h[1]), h23 = __halves2half2(h[2], h[3]);
        __half2 l01 = __halves2half2(l[0], l[1]), l23 = __halves2half2(l[2], l[3]);
        ((__half2*)(r))[0] = h01;        ((__half2*)(r))[1] = h23;
        ((__half2*)(r + 1024))[0] = h01; ((__half2*)(r + 1024))[1] = h23;
        ((__half2*)(r + 2048))[0] = l01; ((__half2*)(r + 2048))[1] = l23;
    } else {
        int wr = row - T_TOKENS;
        float4 v = reinterpret_cast<const float4*>(w)[(size_t)wr * 256 + (c4 >> 2)];
        float vv[4] = {v.x * 32.f, v.y * 32.f, v.z * 32.f, v.w * 32.f};
#pragma unroll
        for (int q = 0; q < 4; q++) {
            h[q] = __float2half_rn(vv[q]);
            l[q] = __float2half_rn(vv[q] - __half2float(h[q]));
        }
        __half* r = g_wr1split + (size_t)wr * KR_DIM + c4;
        __half2 h01 = __halves2half2(h[0], h[1]), h23 = __halves2half2(h[2], h[3]);
        __half2 l01 = __halves2half2(l[0], l[1]), l23 = __halves2half2(l[2], l[3]);
        ((__half2*)(r))[0] = h01;        ((__half2*)(r))[1] = h23;
        ((__half2*)(r + 1024))[0] = l01; ((__half2*)(r + 1024))[1] = l23;
        ((__half2*)(r + 2048))[0] = h01; ((__half2*)(r + 2048))[1] = h23;
    }
}

// ---------------- unified HMMA GEMM -----------------------------------------
// MODE 0: router  h = gelu((1/32)*A'B'^T + br1) -> g_hrouter fp32, M dense
// MODE 1: UP      He = gelu(xh@W1[e]^T + b1[e]) fp16, gathered (token=slot>>1)
// MODE 2: DOWN    Ypart = He@W2[e]^T (+b2 on z=0), gathered, K split by z
// CTA tile 128x128, K-chunk 64 (128B rows), 3-stage cp.async, 256 thr,
// TWO CTAs per SM (latency hiding across barriers/epilogues).
#define OFF_STAGE  1024
#define STAGE_BYTES 32768           // A 16KB + B 16KB
#define SMEM_TOTAL (OFF_STAGE + 3 * STAGE_BYTES)

template <int MODE>
__global__ void __launch_bounds__(256, 2) moe_gemm_kernel(const float* __restrict__ bias_in)
{
    constexpr int K_DIM = (MODE == 0) ? KR_DIM : (MODE == 1 ? 1024 : 4096);
    constexpr int A_STRIDE = (MODE == 2) ? 4096 : KR_DIM;
    constexpr int K_LOCAL = (MODE == 2) ? 2048 : K_DIM;
    constexpr int NITER = K_LOCAL / 64;

    extern __shared__ char smem[];
    const uint32_t sb = smem_to_u32(smem);
    int* sSlot = (int*)smem;
    const int tid = threadIdx.x;
    const int wid = tid >> 5;
    const int lane = tid & 31;
    const int n0 = blockIdx.x * 128;
    const int kz = (MODE == 2) ? blockIdx.z : 0;
    const size_t kBase = (size_t)kz * 2048 * 2;   // bytes along K

    int m0 = 0, eIdx = 0;
    if (MODE == 0) {
        m0 = blockIdx.y * 128;
    } else {
        int mt = blockIdx.y;
        eIdx = -1;
        int pos0 = 0, segEnd = 0;
        int tS = 0, off = 0;
#pragma unroll
        for (int e = 0; e < E_NUM; e++) {
            int cnt = g_counts[e];
            int tiles = (cnt + 127) >> 7;
            if (eIdx < 0 && mt >= tS && mt < tS + tiles) {
                eIdx = e;
                pos0 = off + (mt - tS) * 128;
                segEnd = off + cnt;
            }
            tS += tiles;
            off += cnt;
        }
        if (eIdx < 0) return;
        if (tid < 128) {
            int p = pos0 + tid;
            sSlot[tid] = (p < segEnd) ? g_perm[p] : -1;
        }
    }
    __syncthreads();

    const __half* Abase = (MODE == 2) ? g_He : g_xsplit;
    const __half* Bbase;
    const float* bptr;
    if (MODE == 0)      { Bbase = g_wr1split;                              bptr = bias_in; }
    else if (MODE == 1) { Bbase = g_W1h + (size_t)eIdx * (H_DIM * D_DIM);  bptr = bias_in + eIdx * H_DIM; }
    else                { Bbase = g_W2h + (size_t)eIdx * (D_DIM * H_DIM);  bptr = bias_in + eIdx * D_DIM; }

    // Per-thread A-gather rows: 128 rows x 8 chunks / 256 thr = 4 per thread
    int aRow[4];
    uint32_t aSz[4];
#pragma unroll
    for (int j = 0; j < 4; j++) {
        int r = (tid + j * 256) >> 3;
        aSz[j] = 16;
        if (MODE == 0) aRow[j] = m0 + r;
        else {
            int slot = sSlot[r];
            if (slot < 0) { aRow[j] = 0; aSz[j] = 0; }   // sz=0 -> cp.async zero-fill
            else aRow[j] = (MODE == 1) ? (slot >> 1) : slot;
        }
    }

    // ---- stage loader (A: 128 rows x 128B gathered; B: 128 rows x 128B) ----
    auto load_stage = [&](int it) {
        const uint32_t so = sb + OFF_STAGE + (uint32_t)(it % 3) * STAGE_BYTES;
        const size_t kb = kBase + (size_t)it * 128;
#pragma unroll
        for (int j = 0; j < 4; j++) {
            int c = tid + j * 256;          // 0..1023
            int r = c >> 3;                 // 0..127
            int kc = (c & 7) << 4;          // 0..112
            uint32_t dst = so + (uint32_t)(r * 128 + (kc ^ ((r & 7) << 4)));
            const char* src = (const char*)(Abase + (size_t)aRow[j] * A_STRIDE) + kb + kc;
            CP_ASYNC16(dst, src, aSz[j]);
        }
#pragma unroll
        for (int j = 0; j < 4; j++) {
            int c = tid + j * 256;
            int r = c >> 3;
            int kc = (c & 7) << 4;
            uint32_t dst = so + 16384u + (uint32_t)(r * 128 + (kc ^ ((r & 7) << 4)));
            const char* src = (const char*)(Bbase + (size_t)(n0 + r) * K_DIM) + kb + kc;
            CP_ASYNC16(dst, src, 16u);
        }
    };

    // warp grid: 2 (M) x 4 (N); warp tile 64x32
    const int wm = (wid & 1) * 64;
    const int wn = (wid >> 1) * 32;

    float acc[4][4][4];
#pragma unroll
    for (int i = 0; i < 4; i++)
#pragma unroll
        for (int j = 0; j < 4; j++)
#pragma unroll
            for (int k = 0; k < 4; k++) acc[i][j][k] = 0.f;

    load_stage(0);
    CP_COMMIT();
    load_stage(1);
    CP_COMMIT();

    for (int it = 0; it < NITER; ++it) {
        CP_WAIT1();                   // stage `it` resident; it+1 may be in flight
        __syncthreads();              // loads visible; compute(it-1) finished
        if (it + 2 < NITER) { load_stage(it + 2); CP_COMMIT(); }  // buf (it-1)%3

        const uint32_t aOff = sb + OFF_STAGE + (uint32_t)(it % 3) * STAGE_BYTES;
        const uint32_t bOff = aOff + 16384u;

#pragma unroll
        for (int ks = 0; ks < 4; ks++) {
            const int kb32 = ks * 32;   // byte offset along 128B row
            uint32_t af[4][4];
#pragma unroll
            for (int mf = 0; mf < 4; mf++) {
                int r = wm + mf * 16 + (lane & 15);
                int col = kb32 + ((lane >> 4) << 4);
                uint32_t a = aOff + (uint32_t)(r * 128 + (col ^ ((r & 7) << 4)));
                asm volatile(
                    "ldmatrix.sync.aligned.m8n8.x4.shared.b16 {%0,%1,%2,%3}, [%4];"
                    : "=r"(af[mf][0]), "=r"(af[mf][1]), "=r"(af[mf][2]), "=r"(af[mf][3])
                    : "r"(a));
            }
            uint32_t bf[4][2];
#pragma unroll
            for (int np = 0; np < 2; np++) {
                int r = wn + np * 16 + ((lane >> 4) << 3) + (lane & 7);
                int col = kb32 + ((lane >> 3) & 1) * 16;
                uint32_t a = bOff + (uint32_t)(r * 128 + (col ^ ((r & 7) << 4)));
                asm volatile(
                    "ldmatrix.sync.aligned.m8n8.x4.shared.b16 {%0,%1,%2,%3}, [%4];"
                    : "=r"(bf[2 * np][0]), "=r"(bf[2 * np][1]),
                      "=r"(bf[2 * np + 1][0]), "=r"(bf[2 * np + 1][1])
                    : "r"(a));
            }
#pragma unroll
            for (int mf = 0; mf < 4; mf++)
#pragma unroll
                for (int nf = 0; nf < 4; nf++) {
                    asm volatile(
                        "mma.sync.aligned.m16n8k16.row.col.f32.f16.f16.f32 "
                        "{%0,%1,%2,%3}, {%4,%5,%6,%7}, {%8,%9}, {%0,%1,%2,%3};"
                        : "+f"(acc[mf][nf][0]), "+f"(acc[mf][nf][1]),
                          "+f"(acc[mf][nf][2]), "+f"(acc[mf][nf][3])
                        : "r"(af[mf][0]), "r"(af[mf][1]), "r"(af[mf][2]), "r"(af[mf][3]),
                          "r"(bf[nf][0]), "r"(bf[nf][1]));
                }
        }
    }

    // ---- epilogue ----
    const int lr = lane >> 2;
    const int lc = (lane & 3) * 2;
    float* ybase = g_Y + (size_t)kz * (SLOTS * D_DIM);
    const bool addB = (MODE != 2) || (kz == 0);
#pragma unroll
    for (int mf = 0; mf < 4; mf++) {
#pragma unroll
        for (int h = 0; h < 2; h++) {
            int rl = wm + mf * 16 + lr + h * 8;
            int orow;
            if (MODE == 0) orow = m0 + rl;
            else {
                int slot = sSlot[rl];
                if (slot < 0) continue;
                orow = slot;
            }
#pragma unroll
            for (int nf = 0; nf < 4; nf++) {
                int col = n0 + wn + nf * 8 + lc;
                float v0 = acc[mf][nf][h * 2 + 0];
                float v1 = acc[mf][nf][h * 2 + 1];
                if (MODE == 0) {
                    v0 = gelu_exact(v0 * 0.03125f + bptr[col]);
                    v1 = gelu_exact(v1 * 0.03125f + bptr[col + 1]);
                    *reinterpret_cast<float2*>(&g_hrouter[(size_t)orow * R_DIM + col]) =
                        make_float2(v0, v1);
                } else if (MODE == 1) {
                    v0 = gelu_exact(v0 + bptr[col]);
                    v1 = gelu_exact(v1 + bptr[col + 1]);
                    *reinterpret_cast<__half2*>(&g_He[(size_t)orow * H_DIM + col]) =
                        __floats2half2_rn(v0, v1);
                } else {
                    if (addB) { v0 += bptr[col]; v1 += bptr[col + 1]; }
                    *reinterpret_cast<float2*>(&ybase[(size_t)orow * D_DIM + col]) =
                        make_float2(v0, v1);
                }
            }
        }
    }
}

// ---------------- router stage 2: logits, softmax, top-2 -------------------
__global__ void router_topk_kernel(const float* __restrict__ Wr2,
                                   const float* __restrict__ br2)
{
    int warp = threadIdx.x >> 5;
    int lane = threadIdx.x & 31;
    int t = blockIdx.x * 8 + warp;
    const float* h = g_hrouter + (size_t)t * R_DIM;

    float acc[E_NUM];
#pragma unroll
    for (int e = 0; e < E_NUM; e++) acc[e] = 0.f;
#pragma unroll
    for (int j = 0; j < 16; j++) {
        int i = lane + 32 * j;
        float hv = h[i];
#pragma unroll
        for (int e = 0; e < E_NUM; e++) acc[e] += hv * Wr2[e * R_DIM + i];
    }
#pragma unroll
    for (int off = 16; off > 0; off >>= 1)
#pragma unroll
        for (int e = 0; e < E_NUM; e++)
            acc[e] += __shfl_xor_sync(0xffffffffu, acc[e], off);

    if (lane == 0) {
        float l[E_NUM];
#pragma unroll
        for (int e = 0; e < E_NUM; e++) l[e] = acc[e] + br2[e];
        int i0 = 0; float v0 = l[0];
#pragma unroll
        for (int e = 1; e < E_NUM; e++) if (l[e] > v0) { v0 = l[e]; i0 = e; }
        int i1 = -1; float v1 = -1e30f;
#pragma unroll
        for (int e = 0; e < E_NUM; e++) if (e != i0 && l[e] > v1) { v1 = l[e]; i1 = e; }
        float m = v0;
        float s = 0.f;
#pragma unroll
        for (int e = 0; e < E_NUM; e++) s += expf(l[e] - m);
        float w0 = expf(v0 - m) / s;
        float w1 = expf(v1 - m) / s;
        g_expIdx[2 * t] = i0;     g_expIdx[2 * t + 1] = i1;
        g_expW[2 * t] = w0;       g_expW[2 * t + 1] = w1;
        atomicAdd(&g_counts[i0], 1);
        atomicAdd(&g_counts[i1], 1);
    }
}

// ---------------- fill: segment offsets derived in-register ----------------
__global__ void fill_kernel() {
    int s = blockIdx.x * blockDim.x + threadIdx.x;
    if (s >= SLOTS) return;
    int e = g_expIdx[s];
    int offs = 0;
#pragma unroll
    for (int q = 0; q < E_NUM; q++) {
        int c = g_counts[q];
        if (q < e) offs += c;
    }
    int rank = atomicAdd(&g_fillpos[e], 1);
    g_perm[offs + rank] = s;
}

// ---------------- combine --------------------------------------------------
__global__ void combine_kernel(float* __restrict__ out) {
    int i = blockIdx.x * blockDim.x + threadIdx.x;
    int t = i >> 8;
    int c = i & 255;
    float w0 = g_expW[2 * t];
    float w1 = g_expW[2 * t + 1];
    const float4* Ya = reinterpret_cast<const float4*>(g_Y);
    const float4* Yb = Ya + (size_t)SLOTS * D_DIM / 4;
    float4 a0 = Ya[(size_t)(2 * t) * 256 + c];
    float4 b0 = Yb[(size_t)(2 * t) * 256 + c];
    float4 a1 = Ya[(size_t)(2 * t + 1) * 256 + c];
    float4 b1 = Yb[(size_t)(2 * t + 1) * 256 + c];
    float4 r;
    r.x = w0 * (a0.x + b0.x) + w1 * (a1.x + b1.x);
    r.y = w0 * (a0.y + b0.y) + w1 * (a1.y + b1.y);
    r.z = w0 * (a0.z + b0.z) + w1 * (a1.z + b1.z);
    r.w = w0 * (a0.w + b0.w) + w1 * (a1.w + b1.w);
    reinterpret_cast<float4*>(out)[i] = r;
}

// ---------------- launch ----------------------------------------------------
extern "C" void kernel_launch(void* const* d_in, const int* in_sizes, int n_in,
                              void* d_out, int out_size) {
    const float* x   = (const float*)d_in[0];
    const float* Wr1 = (const float*)d_in[1];
    const float* br1 = (const float*)d_in[2];
    const float* Wr2 = (const float*)d_in[3];
    const float* br2 = (const float*)d_in[4];
    const float* W1  = (const float*)d_in[5];
    const float* b1  = (const float*)d_in[6];
    const float* W2  = (const float*)d_in[7];
    const float* b2  = (const float*)d_in[8];
    float* out = (float*)d_out;

    static cudaStream_t sW = nullptr;
    static cudaEvent_t evFork = nullptr, evW = nullptr;
    if (sW == nullptr) {
        cudaStreamCreateWithFlags(&sW, cudaStreamNonBlocking);
        cudaEventCreateWithFlags(&evFork, cudaEventDisableTiming);
        cudaEventCreateWithFlags(&evW, cudaEventDisableTiming);
        cudaFuncSetAttribute(moe_gemm_kernel<0>, cudaFuncAttributeMaxDynamicSharedMemorySize, SMEM_TOTAL);
        cudaFuncSetAttribute(moe_gemm_kernel<1>, cudaFuncAttributeMaxDynamicSharedMemorySize, SMEM_TOTAL);
        cudaFuncSetAttribute(moe_gemm_kernel<2>, cudaFuncAttributeMaxDynamicSharedMemorySize, SMEM_TOTAL);
    }

    // Fork: W1/W2 conversion concurrent with router chain
    cudaEventRecord(evFork, 0);
    cudaStreamWaitEvent(sW, evFork, 0);
    {
        int n4 = E_NUM * H_DIM * D_DIM / 4;
        conv_kernel<<<2 * n4 / 256, 256, 0, sW>>>(W1, W2, n4);
    }
    cudaEventRecord(evW, sW);

    // Router chain
    split_kernel<<<((T_TOKENS + R_DIM) * 256) / 256, 256>>>(x, Wr1);
    moe_gemm_kernel<0><<<dim3(R_DIM / 128, 64, 1), 256, SMEM_TOTAL>>>(br1);
    router_topk_kernel<<<T_TOKENS / 8, 256>>>(Wr2, br2);
    fill_kernel<<<SLOTS / 256, 256>>>();

    // Experts
    cudaStreamWaitEvent(0, evW, 0);
    moe_gemm_kernel<1><<<dim3(H_DIM / 128, MAX_TILES, 1), 256, SMEM_TOTAL>>>(b1);
    moe_gemm_kernel<2><<<dim3(D_DIM / 128, MAX_TILES, 2), 256, SMEM_TOTAL>>>(b2);

    combine_kernel<<<T_TOKENS * D_DIM / 4 / 256, 256>>>(out);
}